// round 4
// baseline (speedup 1.0000x reference)
#include <cuda_runtime.h>
#include <math.h>

#define T_  512
#define N_  256
#define H_  256
#define HR_ 64
#define V_  64

typedef unsigned long long U64;

__device__ __forceinline__ U64 pack_dup(float x){ U64 r; asm("mov.b64 %0, {%1, %1};" : "=l"(r) : "f"(x)); return r; }
__device__ __forceinline__ U64 fma2(U64 a, U64 b, U64 c){ U64 d; asm("fma.rn.f32x2 %0, %1, %2, %3;" : "=l"(d) : "l"(a), "l"(b), "l"(c)); return d; }
__device__ __forceinline__ float2 u2f(U64 v){ float2 f; asm("mov.b64 {%0, %1}, %2;" : "=f"(f.x), "=f"(f.y) : "l"(v)); return f; }
__device__ __forceinline__ float sigm(float x){ return 1.f / (1.f + expf(-x)); }

// ---------------- scratch (device globals; allocation is forbidden) ------------
__device__ float d_M  [N_*HR_*H_];            // (n,hr,H)
__device__ float d_GIf[N_*HR_*3*H_];          // rows (n*64+s), 768
__device__ float d_GIb[N_*HR_*3*H_];
__device__ float d_K  [N_*HR_*2*H_];          // (n,hr,512) [Kf|Kb]
__device__ float d_Xin[T_*N_*(V_+H_)];        // (t*256+n, 320)
__device__ float d_X0 [T_*N_*H_];
__device__ float d_X1 [T_*N_*H_];
__device__ float d_GIc[T_*N_*3*H_];
__device__ float d_H  [T_*N_*H_];
__device__ float d_Kq [T_*N_*2*H_];
__device__ float d_Lg [T_*N_*HR_];
__device__ float d_Z  [N_*H_];                // zeros (never written)

// ---------------- fp32 GEMM (FFMA2): C = op(A@B + bias) ------------------------
// tile 128x64, 256 threads; acc = 4 row-pairs x 4 cols in f32x2.
template<bool RELU>
__global__ void __launch_bounds__(256) gemm_nn(
    const float* __restrict__ A, int lda,
    const float* __restrict__ B, int ldb,
    const float* __restrict__ bias,
    float* __restrict__ C, int ldc, int Kd)
{
    __shared__ __align__(16) float As[16][128];
    __shared__ __align__(16) float Bs[16][64];
    const int m0 = blockIdx.y * 128;
    const int n0 = blockIdx.x * 64;
    const int tid = threadIdx.x;
    const int tx = tid & 15;          // col group (4 cols)
    const int ty = tid >> 4;          // row group (8 rows = 4 pairs)
    U64 acc[4][4] = {};
    for (int k0 = 0; k0 < Kd; k0 += 16){
        #pragma unroll
        for (int l = 0; l < 2; l++){
            int q = tid + l*256;
            int row = q >> 2, c4 = q & 3;
            float4 f = *(const float4*)&A[(size_t)(m0+row)*lda + k0 + c4*4];
            As[c4*4+0][row] = f.x; As[c4*4+1][row] = f.y;
            As[c4*4+2][row] = f.z; As[c4*4+3][row] = f.w;
        }
        {
            int kr = tid >> 4, c4 = tid & 15;
            *(float4*)&Bs[kr][c4*4] = *(const float4*)&B[(size_t)(k0+kr)*ldb + n0 + c4*4];
        }
        __syncthreads();
        #pragma unroll
        for (int k = 0; k < 16; k++){
            const U64* ap = (const U64*)&As[k][ty*8];
            U64 a0 = ap[0], a1 = ap[1], a2 = ap[2], a3 = ap[3];
            float4 bv = *(const float4*)&Bs[k][tx*4];
            U64 b0 = pack_dup(bv.x), b1 = pack_dup(bv.y);
            U64 b2 = pack_dup(bv.z), b3 = pack_dup(bv.w);
            acc[0][0]=fma2(a0,b0,acc[0][0]); acc[0][1]=fma2(a0,b1,acc[0][1]);
            acc[0][2]=fma2(a0,b2,acc[0][2]); acc[0][3]=fma2(a0,b3,acc[0][3]);
            acc[1][0]=fma2(a1,b0,acc[1][0]); acc[1][1]=fma2(a1,b1,acc[1][1]);
            acc[1][2]=fma2(a1,b2,acc[1][2]); acc[1][3]=fma2(a1,b3,acc[1][3]);
            acc[2][0]=fma2(a2,b0,acc[2][0]); acc[2][1]=fma2(a2,b1,acc[2][1]);
            acc[2][2]=fma2(a2,b2,acc[2][2]); acc[2][3]=fma2(a2,b3,acc[2][3]);
            acc[3][0]=fma2(a3,b0,acc[3][0]); acc[3][1]=fma2(a3,b1,acc[3][1]);
            acc[3][2]=fma2(a3,b2,acc[3][2]); acc[3][3]=fma2(a3,b3,acc[3][3]);
        }
        __syncthreads();
    }
    float4 bb = *(const float4*)&bias[n0 + tx*4];
    #pragma unroll
    for (int p = 0; p < 4; p++){
        float2 v0 = u2f(acc[p][0]);
        float2 v1 = u2f(acc[p][1]);
        float2 v2 = u2f(acc[p][2]);
        float2 v3 = u2f(acc[p][3]);
        float4 o0, o1;
        o0.x = v0.x + bb.x; o0.y = v1.x + bb.y; o0.z = v2.x + bb.z; o0.w = v3.x + bb.w;
        o1.x = v0.y + bb.x; o1.y = v1.y + bb.y; o1.z = v2.y + bb.z; o1.w = v3.y + bb.w;
        if (RELU){
            o0.x = fmaxf(o0.x,0.f); o0.y = fmaxf(o0.y,0.f); o0.z = fmaxf(o0.z,0.f); o0.w = fmaxf(o0.w,0.f);
            o1.x = fmaxf(o1.x,0.f); o1.y = fmaxf(o1.y,0.f); o1.z = fmaxf(o1.z,0.f); o1.w = fmaxf(o1.w,0.f);
        }
        int r0 = m0 + ty*8 + p*2;
        *(float4*)&C[(size_t)r0*ldc     + n0 + tx*4] = o0;
        *(float4*)&C[(size_t)(r0+1)*ldc + n0 + tx*4] = o1;
    }
}

// ---------------- gather Xin = [values ; M[n, a_prev]] -------------------------
__global__ void gather_xin(const float* __restrict__ values,
                           const int* __restrict__ actions,
                           const int* __restrict__ a0)
{
    int idx = blockIdx.x * blockDim.x + threadIdx.x;   // one float4
    const int TOT = T_*N_*80;
    if (idx >= TOT) return;
    int i   = idx / 80;        // row (t*256+n)
    int c4  = idx % 80;
    float4 f;
    if (c4 < 16){
        f = *(const float4*)&values[(size_t)i*64 + c4*4];
    } else {
        int t = i >> 8, n = i & 255;
        int ap = (t == 0) ? a0[n] : actions[i - 256];
        f = *(const float4*)&d_M[((size_t)n*64 + ap)*256 + (c4-16)*4];
    }
    *(float4*)&d_Xin[(size_t)i*320 + c4*4] = f;
}

// ---------------- fused GRU step: h_new = GRU(gi_t, h_prev) --------------------
struct GruP {
    const float* gi; int gi_stride;   // row = gi + n*stride (768: r|z|n)
    const float* hp; int hp_stride;
    float*       ho; int ho_stride;
    const float* Whh;                 // (256,768)
    const float* bhh;                 // (768)
};

// block: 32 batch rows x 16 h-cols (x3 gates); grid: (16, 8, nz) = 128 CTAs/dir
__global__ void __launch_bounds__(256) gru_step(GruP pa, GruP pb)
{
    GruP P = (blockIdx.z == 0) ? pa : pb;
    const int rowBase = blockIdx.y * 32;
    const int hcBase  = blockIdx.x * 16;
    __shared__ __align__(16) float Hs[16][32];
    __shared__ __align__(16) U64   Ws[16][48];   // pre-duplicated weights
    const int tid = threadIdx.x;
    const int tx = tid & 15;          // h-col
    const int ty = tid >> 4;          // row pair (16 pairs = 32 rows)
    U64 acc[3] = {};
    for (int k0 = 0; k0 < 256; k0 += 16){
        if (tid < 128){
            int row = tid >> 2, c4 = tid & 3;
            float4 f = *(const float4*)&P.hp[(size_t)(rowBase+row)*P.hp_stride + k0 + c4*4];
            Hs[c4*4+0][row] = f.x; Hs[c4*4+1][row] = f.y;
            Hs[c4*4+2][row] = f.z; Hs[c4*4+3][row] = f.w;
        }
        #pragma unroll
        for (int l = 0; l < 3; l++){
            int q = tid + l*256;          // 0..767
            int kr = q / 48, cc = q % 48;
            int g = cc >> 4, c = cc & 15;
            Ws[kr][cc] = pack_dup(P.Whh[(size_t)(k0+kr)*768 + g*256 + hcBase + c]);
        }
        __syncthreads();
        #pragma unroll
        for (int k = 0; k < 16; k++){
            U64 a = ((const U64*)&Hs[k][0])[ty];
            acc[0] = fma2(a, Ws[k][tx],      acc[0]);
            acc[1] = fma2(a, Ws[k][16 + tx], acc[1]);
            acc[2] = fma2(a, Ws[k][32 + tx], acc[2]);
        }
        __syncthreads();
    }
    const int hcol = hcBase + tx;
    float br = P.bhh[hcol], bz = P.bhh[256 + hcol], bn = P.bhh[512 + hcol];
    float2 ar = u2f(acc[0]), az = u2f(acc[1]), an = u2f(acc[2]);
    #pragma unroll
    for (int r = 0; r < 2; r++){
        int row = rowBase + ty*2 + r;
        const float* gi = P.gi + (size_t)row * P.gi_stride;
        float ghr = (r == 0) ? ar.x : ar.y;
        float ghz = (r == 0) ? az.x : az.y;
        float ghn = (r == 0) ? an.x : an.y;
        float hpv = P.hp[(size_t)row*P.hp_stride + hcol];
        float rr = sigm(gi[hcol]       + ghr + br);
        float zz = sigm(gi[256 + hcol] + ghz + bz);
        float nn = tanhf(gi[512 + hcol] + rr*(ghn + bn));
        P.ho[(size_t)row*P.ho_stride + hcol] = (1.f - zz)*nn + zz*hpv;
    }
}

// ---------------- logits (FFMA2): per-n  Lg[t,n,s] = Kq[t,n,:] . K[n,s,:] -------
// grid (t-tile 4, n 256), block 256; tile 128(t) x 64(s) x 512
__global__ void __launch_bounds__(256) logits_gemm()
{
    const int n  = blockIdx.y;
    const int m0 = blockIdx.x * 128;
    const float* Aq = d_Kq + (size_t)n*512;          // row t: + t*131072
    const float* Kn = d_K  + (size_t)n*32768;        // row s: + s*512
    __shared__ __align__(16) float As[16][128];
    __shared__ __align__(16) float Bs[16][64];
    const int tid = threadIdx.x;
    const int tx = tid & 15;
    const int ty = tid >> 4;
    U64 acc[4][4] = {};
    for (int k0 = 0; k0 < 512; k0 += 16){
        #pragma unroll
        for (int l = 0; l < 2; l++){
            int q = tid + l*256;
            int row = q >> 2, c4 = q & 3;
            float4 f = *(const float4*)&Aq[(size_t)(m0+row)*131072 + k0 + c4*4];
            As[c4*4+0][row] = f.x; As[c4*4+1][row] = f.y;
            As[c4*4+2][row] = f.z; As[c4*4+3][row] = f.w;
        }
        {
            int srow = tid >> 2, c4 = tid & 3;
            float4 f = *(const float4*)&Kn[(size_t)srow*512 + k0 + c4*4];
            Bs[c4*4+0][srow] = f.x; Bs[c4*4+1][srow] = f.y;
            Bs[c4*4+2][srow] = f.z; Bs[c4*4+3][srow] = f.w;
        }
        __syncthreads();
        #pragma unroll
        for (int k = 0; k < 16; k++){
            const U64* ap = (const U64*)&As[k][ty*8];
            U64 a0 = ap[0], a1 = ap[1], a2 = ap[2], a3 = ap[3];
            float4 bv = *(const float4*)&Bs[k][tx*4];
            U64 b0 = pack_dup(bv.x), b1 = pack_dup(bv.y);
            U64 b2 = pack_dup(bv.z), b3 = pack_dup(bv.w);
            acc[0][0]=fma2(a0,b0,acc[0][0]); acc[0][1]=fma2(a0,b1,acc[0][1]);
            acc[0][2]=fma2(a0,b2,acc[0][2]); acc[0][3]=fma2(a0,b3,acc[0][3]);
            acc[1][0]=fma2(a1,b0,acc[1][0]); acc[1][1]=fma2(a1,b1,acc[1][1]);
            acc[1][2]=fma2(a1,b2,acc[1][2]); acc[1][3]=fma2(a1,b3,acc[1][3]);
            acc[2][0]=fma2(a2,b0,acc[2][0]); acc[2][1]=fma2(a2,b1,acc[2][1]);
            acc[2][2]=fma2(a2,b2,acc[2][2]); acc[2][3]=fma2(a2,b3,acc[2][3]);
            acc[3][0]=fma2(a3,b0,acc[3][0]); acc[3][1]=fma2(a3,b1,acc[3][1]);
            acc[3][2]=fma2(a3,b2,acc[3][2]); acc[3][3]=fma2(a3,b3,acc[3][3]);
        }
        __syncthreads();
    }
    #pragma unroll
    for (int p = 0; p < 4; p++){
        int t0 = m0 + ty*8 + p*2;
        #pragma unroll
        for (int j = 0; j < 4; j++){
            float2 v = u2f(acc[p][j]);
            d_Lg[((size_t)t0*256 + n)*64 + tx*4 + j]     = v.x;
            d_Lg[((size_t)(t0+1)*256 + n)*64 + tx*4 + j] = v.y;
        }
    }
}

// ---------------- pack: out[t,n] = [action, critic, h(256), softmax(64)] --------
__global__ void __launch_bounds__(256) pack_out(
    const int* __restrict__ actions,
    const float* __restrict__ critic_W, const float* __restrict__ critic_b,
    float* __restrict__ out)
{
    int wid  = blockIdx.x*8 + (threadIdx.x >> 5);   // (t*256+n)
    int lane = threadIdx.x & 31;
    const float* h  = d_H  + (size_t)wid*256;
    const float* lg = d_Lg + (size_t)wid*64;
    float* o = out + (size_t)wid*322;

    float c = 0.f;
    #pragma unroll
    for (int j = 0; j < 8; j++){
        int k = lane + j*32;
        c += h[k]*critic_W[k];
    }
    #pragma unroll
    for (int s = 16; s > 0; s >>= 1) c += __shfl_xor_sync(0xffffffffu, c, s);

    #pragma unroll
    for (int j = 0; j < 8; j++){
        int k = lane + j*32;
        o[2 + k] = h[k];
    }

    float x0 = lg[lane], x1 = lg[lane + 32];
    float m = fmaxf(x0, x1);
    #pragma unroll
    for (int s = 16; s > 0; s >>= 1) m = fmaxf(m, __shfl_xor_sync(0xffffffffu, m, s));
    float e0 = expf(x0 - m), e1 = expf(x1 - m);
    float ssum = e0 + e1;
    #pragma unroll
    for (int s = 16; s > 0; s >>= 1) ssum += __shfl_xor_sync(0xffffffffu, ssum, s);
    float inv = 1.f / ssum;
    o[258 + lane]      = e0 * inv;
    o[258 + 32 + lane] = e1 * inv;

    if (lane == 0){
        o[0] = (float)actions[wid];
        o[1] = c + critic_b[0];
    }
}

// ---------------- host orchestration -------------------------------------------
extern "C" void kernel_launch(void* const* d_in, const int* in_sizes, int n_in,
                              void* d_out, int out_size)
{
    const float* values   = (const float*)d_in[0];
    const float* mdp      = (const float*)d_in[1];
    const int*   actions  = (const int*)  d_in[2];
    const int*   a0       = (const int*)  d_in[3];
    const float* h0       = (const float*)d_in[4];
    const float* emb_W    = (const float*)d_in[5];
    const float* emb_b    = (const float*)d_in[6];
    const float* gfw_Wih  = (const float*)d_in[7];
    const float* gfw_Whh  = (const float*)d_in[8];
    const float* gfw_bih  = (const float*)d_in[9];
    const float* gfw_bhh  = (const float*)d_in[10];
    const float* gbw_Wih  = (const float*)d_in[11];
    const float* gbw_Whh  = (const float*)d_in[12];
    const float* gbw_bih  = (const float*)d_in[13];
    const float* gbw_bhh  = (const float*)d_in[14];
    const float* f0_W     = (const float*)d_in[15];
    const float* f0_b     = (const float*)d_in[16];
    const float* f1_W     = (const float*)d_in[17];
    const float* f1_b     = (const float*)d_in[18];
    const float* cell_Wih = (const float*)d_in[19];
    const float* cell_Whh = (const float*)d_in[20];
    const float* cell_bih = (const float*)d_in[21];
    const float* cell_bhh = (const float*)d_in[22];
    const float* critic_W = (const float*)d_in[23];
    const float* critic_b = (const float*)d_in[24];
    const float* qg_W     = (const float*)d_in[25];
    const float* qg_b     = (const float*)d_in[26];
    float* out = (float*)d_out;

    float *pM, *pGIf, *pGIb, *pK, *pXin, *pX0, *pX1, *pGIc, *pH, *pKq, *pZ;
    cudaGetSymbolAddress((void**)&pM,   d_M);
    cudaGetSymbolAddress((void**)&pGIf, d_GIf);
    cudaGetSymbolAddress((void**)&pGIb, d_GIb);
    cudaGetSymbolAddress((void**)&pK,   d_K);
    cudaGetSymbolAddress((void**)&pXin, d_Xin);
    cudaGetSymbolAddress((void**)&pX0,  d_X0);
    cudaGetSymbolAddress((void**)&pX1,  d_X1);
    cudaGetSymbolAddress((void**)&pGIc, d_GIc);
    cudaGetSymbolAddress((void**)&pH,   d_H);
    cudaGetSymbolAddress((void**)&pKq,  d_Kq);
    cudaGetSymbolAddress((void**)&pZ,   d_Z);

    // 1) M = mdp @ emb_W + emb_b            (16384,128)@(128,256)
    gemm_nn<false><<<dim3(4,128), 256>>>(mdp, 128, emb_W, 256, emb_b, pM, 256, 128);
    // 2) GIf / GIb = M @ Wih + bih          (16384,256)@(256,768)
    gemm_nn<false><<<dim3(12,128), 256>>>(pM, 256, gfw_Wih, 768, gfw_bih, pGIf, 768, 256);
    gemm_nn<false><<<dim3(12,128), 256>>>(pM, 256, gbw_Wih, 768, gbw_bih, pGIb, 768, 256);
    // 3) Xin gather, X0, X1, GIc
    gather_xin<<<(T_*N_*80 + 255)/256, 256>>>(values, actions, a0);
    gemm_nn<true ><<<dim3(4,1024), 256>>>(pXin, 320, f0_W, 256, f0_b, pX0, 256, 320);
    gemm_nn<true ><<<dim3(4,1024), 256>>>(pX0, 256, f1_W, 256, f1_b, pX1, 256, 256);
    gemm_nn<false><<<dim3(12,1024), 256>>>(pX1, 256, cell_Wih, 768, cell_bih, pGIc, 768, 256);

    // 4) encoder GRUs: 64 steps, fw+bw via gridDim.z=2 (256 CTAs/step)
    for (int s = 0; s < HR_; s++){
        int sb = HR_ - 1 - s;
        GruP pa, pb;
        pa.gi = pGIf + (size_t)s*768;   pa.gi_stride = 64*768;
        pa.hp = (s == 0) ? pZ : pK + (size_t)(s-1)*512;
        pa.hp_stride = (s == 0) ? 256 : 64*512;
        pa.ho = pK + (size_t)s*512;     pa.ho_stride = 64*512;
        pa.Whh = gfw_Whh; pa.bhh = gfw_bhh;
        pb.gi = pGIb + (size_t)sb*768;  pb.gi_stride = 64*768;
        pb.hp = (s == 0) ? pZ : pK + (size_t)(sb+1)*512 + 256;
        pb.hp_stride = (s == 0) ? 256 : 64*512;
        pb.ho = pK + (size_t)sb*512 + 256; pb.ho_stride = 64*512;
        pb.Whh = gbw_Whh; pb.bhh = gbw_bhh;
        gru_step<<<dim3(16,8,2), 256>>>(pa, pb);
    }

    // 5) cell GRU: 512 steps (128 CTAs/step)
    for (int t = 0; t < T_; t++){
        GruP pa;
        pa.gi = pGIc + (size_t)t*N_*768; pa.gi_stride = 768;
        pa.hp = (t == 0) ? h0 : pH + (size_t)(t-1)*N_*256;
        pa.hp_stride = 256;
        pa.ho = pH + (size_t)t*N_*256;   pa.ho_stride = 256;
        pa.Whh = cell_Whh; pa.bhh = cell_bhh;
        gru_step<<<dim3(16,8,1), 256>>>(pa, pa);
    }

    // 6) Kq = H @ qg_W + qg_b               (131072,256)@(256,512)
    gemm_nn<false><<<dim3(8,1024), 256>>>(pH, 256, qg_W, 512, qg_b, pKq, 512, 256);
    // 7) logits
    logits_gemm<<<dim3(4,256), 256>>>();
    // 8) pack output
    pack_out<<<T_*N_/8, 256>>>(actions, critic_W, critic_b, out);
}

// round 5
// speedup vs baseline: 1.5702x; 1.5702x over previous
#include <cuda_runtime.h>
#include <math.h>

#define T_  512
#define N_  256
#define H_  256
#define HR_ 64
#define V_  64

typedef unsigned long long U64;

__device__ __forceinline__ U64 pack_dup(float x){ U64 r; asm("mov.b64 %0, {%1, %1};" : "=l"(r) : "f"(x)); return r; }
__device__ __forceinline__ U64 fma2(U64 a, U64 b, U64 c){ U64 d; asm("fma.rn.f32x2 %0, %1, %2, %3;" : "=l"(d) : "l"(a), "l"(b), "l"(c)); return d; }
__device__ __forceinline__ float2 u2f(U64 v){ float2 f; asm("mov.b64 {%0, %1}, %2;" : "=f"(f.x), "=f"(f.y) : "l"(v)); return f; }
__device__ __forceinline__ float sigm(float x){ return 1.f / (1.f + expf(-x)); }

__device__ float d_M  [N_*HR_*H_];
__device__ float d_GIf[N_*HR_*3*H_];
__device__ float d_GIb[N_*HR_*3*H_];
__device__ float d_K  [N_*HR_*2*H_];
__device__ float d_Xin[T_*N_*(V_+H_)];
__device__ float d_X0 [T_*N_*H_];
__device__ float d_X1 [T_*N_*H_];
__device__ float d_GIc[T_*N_*3*H_];
__device__ float d_H  [T_*N_*H_];
__device__ float d_Ht [T_*N_*H_];          // transposed per step: [t][col][n]
__device__ float d_Kt [2*HR_*N_*H_];       // [dir][s][col][n]
__device__ float d_Kq [T_*N_*2*H_];
__device__ float d_Lg [T_*N_*HR_];
__device__ unsigned d_barE, d_barC;

__global__ void zero_bars(){ d_barE = 0u; d_barC = 0u; }

// ---------------- fp32 GEMM (FFMA2), tile 128x64 -------------------------------
template<bool RELU>
__global__ void __launch_bounds__(256) gemm_nn(
    const float* __restrict__ A, int lda, const float* __restrict__ B, int ldb,
    const float* __restrict__ bias, float* __restrict__ C, int ldc, int Kd)
{
    __shared__ __align__(16) float As[16][128];
    __shared__ __align__(16) float Bs[16][64];
    const int m0 = blockIdx.y * 128, n0 = blockIdx.x * 64;
    const int tid = threadIdx.x, tx = tid & 15, ty = tid >> 4;
    U64 acc[4][4] = {};
    for (int k0 = 0; k0 < Kd; k0 += 16){
        #pragma unroll
        for (int l = 0; l < 2; l++){
            int q = tid + l*256, row = q >> 2, c4 = q & 3;
            float4 f = *(const float4*)&A[(size_t)(m0+row)*lda + k0 + c4*4];
            As[c4*4+0][row] = f.x; As[c4*4+1][row] = f.y;
            As[c4*4+2][row] = f.z; As[c4*4+3][row] = f.w;
        }
        {
            int kr = tid >> 4, c4 = tid & 15;
            *(float4*)&Bs[kr][c4*4] = *(const float4*)&B[(size_t)(k0+kr)*ldb + n0 + c4*4];
        }
        __syncthreads();
        #pragma unroll
        for (int k = 0; k < 16; k++){
            const U64* ap = (const U64*)&As[k][ty*8];
            U64 a0 = ap[0], a1 = ap[1], a2 = ap[2], a3 = ap[3];
            float4 bv = *(const float4*)&Bs[k][tx*4];
            U64 b0 = pack_dup(bv.x), b1 = pack_dup(bv.y);
            U64 b2 = pack_dup(bv.z), b3 = pack_dup(bv.w);
            acc[0][0]=fma2(a0,b0,acc[0][0]); acc[0][1]=fma2(a0,b1,acc[0][1]);
            acc[0][2]=fma2(a0,b2,acc[0][2]); acc[0][3]=fma2(a0,b3,acc[0][3]);
            acc[1][0]=fma2(a1,b0,acc[1][0]); acc[1][1]=fma2(a1,b1,acc[1][1]);
            acc[1][2]=fma2(a1,b2,acc[1][2]); acc[1][3]=fma2(a1,b3,acc[1][3]);
            acc[2][0]=fma2(a2,b0,acc[2][0]); acc[2][1]=fma2(a2,b1,acc[2][1]);
            acc[2][2]=fma2(a2,b2,acc[2][2]); acc[2][3]=fma2(a2,b3,acc[2][3]);
            acc[3][0]=fma2(a3,b0,acc[3][0]); acc[3][1]=fma2(a3,b1,acc[3][1]);
            acc[3][2]=fma2(a3,b2,acc[3][2]); acc[3][3]=fma2(a3,b3,acc[3][3]);
        }
        __syncthreads();
    }
    float4 bb = *(const float4*)&bias[n0 + tx*4];
    #pragma unroll
    for (int p = 0; p < 4; p++){
        float2 v0 = u2f(acc[p][0]), v1 = u2f(acc[p][1]), v2 = u2f(acc[p][2]), v3 = u2f(acc[p][3]);
        float4 o0, o1;
        o0.x = v0.x+bb.x; o0.y = v1.x+bb.y; o0.z = v2.x+bb.z; o0.w = v3.x+bb.w;
        o1.x = v0.y+bb.x; o1.y = v1.y+bb.y; o1.z = v2.y+bb.z; o1.w = v3.y+bb.w;
        if (RELU){
            o0.x=fmaxf(o0.x,0.f); o0.y=fmaxf(o0.y,0.f); o0.z=fmaxf(o0.z,0.f); o0.w=fmaxf(o0.w,0.f);
            o1.x=fmaxf(o1.x,0.f); o1.y=fmaxf(o1.y,0.f); o1.z=fmaxf(o1.z,0.f); o1.w=fmaxf(o1.w,0.f);
        }
        int r0 = m0 + ty*8 + p*2;
        *(float4*)&C[(size_t)r0*ldc     + n0 + tx*4] = o0;
        *(float4*)&C[(size_t)(r0+1)*ldc + n0 + tx*4] = o1;
    }
}

__global__ void gather_xin(const float* __restrict__ values,
                           const int* __restrict__ actions, const int* __restrict__ a0)
{
    int idx = blockIdx.x * blockDim.x + threadIdx.x;
    if (idx >= T_*N_*80) return;
    int i = idx / 80, c4 = idx % 80;
    float4 f;
    if (c4 < 16) f = *(const float4*)&values[(size_t)i*64 + c4*4];
    else {
        int t = i >> 8, n = i & 255;
        int ap = (t == 0) ? a0[n] : actions[i - 256];
        f = *(const float4*)&d_M[((size_t)n*64 + ap)*256 + (c4-16)*4];
    }
    *(float4*)&d_Xin[(size_t)i*320 + c4*4] = f;
}

// ============ persistent cell chain: 128 CTAs (8 rb x 16 cb), 512 steps =========
__global__ void __launch_bounds__(256,1) cell_chain(
    const float* __restrict__ GIc, const float* __restrict__ h0,
    const float* __restrict__ Whh, const float* __restrict__ bhh, float* __restrict__ H)
{
    extern __shared__ char sm[];
    U64*   Ws = (U64*)sm;                  // [256*48] dup'd
    float* Hs = (float*)(sm + 98304);      // [256 col][32 row]
    const int tid = threadIdx.x, tx = tid & 15, ty = tid >> 4;
    const int rb = (blockIdx.x >> 4) * 32, hcB = (blockIdx.x & 15) * 16, hcol = hcB + tx;
    for (int i = tid; i < 256*48; i += 256){
        int k = i/48, cc = i%48, g = cc>>4, c = cc&15;
        Ws[i] = pack_dup(Whh[(size_t)k*768 + g*256 + hcB + c]);
    }
    const float brv = bhh[hcol], bzv = bhh[256+hcol], bnv = bhh[512+hcol];
    __syncthreads();
    for (int t = 0; t < T_; t++){
        if (t == 0){
            for (int i = tid; i < 2048; i += 256){
                int r = i >> 6, c4 = i & 63;
                float4 f = *(const float4*)&h0[(size_t)(rb+r)*256 + c4*4];
                Hs[(c4*4+0)*32+r]=f.x; Hs[(c4*4+1)*32+r]=f.y;
                Hs[(c4*4+2)*32+r]=f.z; Hs[(c4*4+3)*32+r]=f.w;
            }
        } else {
            const float* hp = d_Ht + (size_t)(t-1)*65536;
            for (int i = tid; i < 2048; i += 256){
                int c = i >> 3, rg = i & 7;
                float4 f = *(const float4*)&hp[(size_t)c*256 + rb + rg*4];
                *(float4*)&Hs[c*32 + rg*4] = f;
            }
        }
        __syncthreads();
        U64 acc0=0ull, acc1=0ull, acc2=0ull;
        const U64* HsU = (const U64*)Hs;
        #pragma unroll 8
        for (int k = 0; k < 256; k++){
            U64 a = HsU[k*16 + ty];
            acc0 = fma2(a, Ws[k*48 + tx],    acc0);
            acc1 = fma2(a, Ws[k*48 + 16+tx], acc1);
            acc2 = fma2(a, Ws[k*48 + 32+tx], acc2);
        }
        float2 gr = u2f(acc0), gz = u2f(acc1), gn = u2f(acc2);
        float ov[2];
        #pragma unroll
        for (int rr = 0; rr < 2; rr++){
            int rl = 2*ty + rr, n = rb + rl;
            const float* gi = GIc + ((size_t)t*256 + n)*768;
            float ghr = rr ? gr.y : gr.x, ghz = rr ? gz.y : gz.x, ghn = rr ? gn.y : gn.x;
            float hpv = Hs[hcol*32 + rl];
            float r_ = sigm(gi[hcol] + ghr + brv);
            float z_ = sigm(gi[256+hcol] + ghz + bzv);
            float n_ = tanhf(gi[512+hcol] + r_*(ghn + bnv));
            ov[rr] = (1.f - z_)*n_ + z_*hpv;
            H[(size_t)t*65536 + n*256 + hcol] = ov[rr];
        }
        *(float2*)&d_Ht[(size_t)t*65536 + hcol*256 + rb + 2*ty] = make_float2(ov[0], ov[1]);
        if (t+1 < T_){
            __threadfence();
            __syncthreads();
            if (tid == 0){
                atomicAdd(&d_barC, 1u);
                unsigned tg = 128u*(t+1);
                while (*(volatile unsigned*)&d_barC < tg) { }
                __threadfence();
            }
            __syncthreads();
        }
    }
}

// ============ persistent encoder chain: 128 CTAs (2 dir x 4 rb x 16 cb) =========
__global__ void __launch_bounds__(256,1) enc_chain(
    const float* __restrict__ GIf, const float* __restrict__ GIb,
    const float* __restrict__ Wf,  const float* __restrict__ Wb,
    const float* __restrict__ bf,  const float* __restrict__ bb,
    float* __restrict__ Kout)
{
    extern __shared__ char sm[];
    U64*   Ws = (U64*)sm;                  // [256*48]
    float* Hs = (float*)(sm + 98304);      // [256 col][64 row]
    const int tid = threadIdx.x, tx = tid & 15, ty = tid >> 4;
    const int dir = blockIdx.x >> 6, b6 = blockIdx.x & 63;
    const int rb = (b6 >> 4)*64, hcB = (b6 & 15)*16, hcol = hcB + tx;
    const float* W  = dir ? Wb  : Wf;
    const float* bh = dir ? bb  : bf;
    const float* GI = dir ? GIb : GIf;
    float* Kt = d_Kt + (size_t)dir*HR_*65536;
    for (int i = tid; i < 256*48; i += 256){
        int k = i/48, cc = i%48, g = cc>>4, c = cc&15;
        Ws[i] = pack_dup(W[(size_t)k*768 + g*256 + hcB + c]);
    }
    const float brv = bh[hcol], bzv = bh[256+hcol], bnv = bh[512+hcol];
    __syncthreads();
    for (int step = 0; step < HR_; step++){
        const int s = dir ? (HR_-1-step) : step;
        if (step == 0){
            for (int i = tid; i < 4096; i += 256) ((float*)Hs)[i*4+0]=0.f,
                ((float*)Hs)[i*4+1]=0.f, ((float*)Hs)[i*4+2]=0.f, ((float*)Hs)[i*4+3]=0.f;
        } else {
            const int sp = dir ? (s+1) : (s-1);
            const float* hp = Kt + (size_t)sp*65536;
            for (int i = tid; i < 4096; i += 256){
                int c = i >> 4, rg = i & 15;
                float4 f = *(const float4*)&hp[(size_t)c*256 + rb + rg*4];
                *(float4*)&Hs[c*64 + rg*4] = f;
            }
        }
        __syncthreads();
        U64 acc[2][3]; acc[0][0]=acc[0][1]=acc[0][2]=0ull; acc[1][0]=acc[1][1]=acc[1][2]=0ull;
        const U64* HsU = (const U64*)Hs;
        #pragma unroll 8
        for (int k = 0; k < 256; k++){
            U64 a0 = HsU[k*32 + 2*ty], a1 = HsU[k*32 + 2*ty + 1];
            U64 b0 = Ws[k*48 + tx], b1 = Ws[k*48 + 16+tx], b2 = Ws[k*48 + 32+tx];
            acc[0][0]=fma2(a0,b0,acc[0][0]); acc[0][1]=fma2(a0,b1,acc[0][1]); acc[0][2]=fma2(a0,b2,acc[0][2]);
            acc[1][0]=fma2(a1,b0,acc[1][0]); acc[1][1]=fma2(a1,b1,acc[1][1]); acc[1][2]=fma2(a1,b2,acc[1][2]);
        }
        float vals[4];
        #pragma unroll
        for (int i = 0; i < 2; i++){
            float2 gr = u2f(acc[i][0]), gz = u2f(acc[i][1]), gn = u2f(acc[i][2]);
            #pragma unroll
            for (int rr = 0; rr < 2; rr++){
                int rl = 4*ty + 2*i + rr, n = rb + rl;
                const float* gi = GI + (size_t)(n*64 + s)*768;
                float ghr = rr ? gr.y : gr.x, ghz = rr ? gz.y : gz.x, ghn = rr ? gn.y : gn.x;
                float hpv = Hs[hcol*64 + rl];
                float r_ = sigm(gi[hcol] + ghr + brv);
                float z_ = sigm(gi[256+hcol] + ghz + bzv);
                float n_ = tanhf(gi[512+hcol] + r_*(ghn + bnv));
                vals[2*i+rr] = (1.f - z_)*n_ + z_*hpv;
                Kout[(size_t)(n*64 + s)*512 + dir*256 + hcol] = vals[2*i+rr];
            }
        }
        *(float4*)&Kt[(size_t)s*65536 + hcol*256 + rb + 4*ty] =
            make_float4(vals[0], vals[1], vals[2], vals[3]);
        if (step+1 < HR_){
            __threadfence();
            __syncthreads();
            if (tid == 0){
                atomicAdd(&d_barE, 1u);
                unsigned tg = 128u*(step+1);
                while (*(volatile unsigned*)&d_barE < tg) { }
                __threadfence();
            }
            __syncthreads();
        }
    }
}

// ---------------- logits: per-n  Lg[t,n,s] = Kq[t,n,:] . K[n,s,:] ---------------
__global__ void __launch_bounds__(256) logits_gemm()
{
    const int n  = blockIdx.y, m0 = blockIdx.x * 128;
    const float* Aq = d_Kq + (size_t)n*512;
    const float* Kn = d_K  + (size_t)n*32768;
    __shared__ __align__(16) float As[16][128];
    __shared__ __align__(16) float Bs[16][64];
    const int tid = threadIdx.x, tx = tid & 15, ty = tid >> 4;
    U64 acc[4][4] = {};
    for (int k0 = 0; k0 < 512; k0 += 16){
        #pragma unroll
        for (int l = 0; l < 2; l++){
            int q = tid + l*256, row = q >> 2, c4 = q & 3;
            float4 f = *(const float4*)&Aq[(size_t)(m0+row)*131072 + k0 + c4*4];
            As[c4*4+0][row]=f.x; As[c4*4+1][row]=f.y; As[c4*4+2][row]=f.z; As[c4*4+3][row]=f.w;
        }
        {
            int srow = tid >> 2, c4 = tid & 3;
            float4 f = *(const float4*)&Kn[(size_t)srow*512 + k0 + c4*4];
            Bs[c4*4+0][srow]=f.x; Bs[c4*4+1][srow]=f.y; Bs[c4*4+2][srow]=f.z; Bs[c4*4+3][srow]=f.w;
        }
        __syncthreads();
        #pragma unroll
        for (int k = 0; k < 16; k++){
            const U64* ap = (const U64*)&As[k][ty*8];
            U64 a0 = ap[0], a1 = ap[1], a2 = ap[2], a3 = ap[3];
            float4 bv = *(const float4*)&Bs[k][tx*4];
            U64 b0 = pack_dup(bv.x), b1 = pack_dup(bv.y);
            U64 b2 = pack_dup(bv.z), b3 = pack_dup(bv.w);
            acc[0][0]=fma2(a0,b0,acc[0][0]); acc[0][1]=fma2(a0,b1,acc[0][1]);
            acc[0][2]=fma2(a0,b2,acc[0][2]); acc[0][3]=fma2(a0,b3,acc[0][3]);
            acc[1][0]=fma2(a1,b0,acc[1][0]); acc[1][1]=fma2(a1,b1,acc[1][1]);
            acc[1][2]=fma2(a1,b2,acc[1][2]); acc[1][3]=fma2(a1,b3,acc[1][3]);
            acc[2][0]=fma2(a2,b0,acc[2][0]); acc[2][1]=fma2(a2,b1,acc[2][1]);
            acc[2][2]=fma2(a2,b2,acc[2][2]); acc[2][3]=fma2(a2,b3,acc[2][3]);
            acc[3][0]=fma2(a3,b0,acc[3][0]); acc[3][1]=fma2(a3,b1,acc[3][1]);
            acc[3][2]=fma2(a3,b2,acc[3][2]); acc[3][3]=fma2(a3,b3,acc[3][3]);
        }
        __syncthreads();
    }
    #pragma unroll
    for (int p = 0; p < 4; p++){
        int t0 = m0 + ty*8 + p*2;
        #pragma unroll
        for (int j = 0; j < 4; j++){
            float2 v = u2f(acc[p][j]);
            d_Lg[((size_t)t0*256 + n)*64 + tx*4 + j]     = v.x;
            d_Lg[((size_t)(t0+1)*256 + n)*64 + tx*4 + j] = v.y;
        }
    }
}

__global__ void __launch_bounds__(256) pack_out(
    const int* __restrict__ actions,
    const float* __restrict__ critic_W, const float* __restrict__ critic_b,
    float* __restrict__ out)
{
    int wid = blockIdx.x*8 + (threadIdx.x >> 5), lane = threadIdx.x & 31;
    const float* h  = d_H  + (size_t)wid*256;
    const float* lg = d_Lg + (size_t)wid*64;
    float* o = out + (size_t)wid*322;
    float c = 0.f;
    #pragma unroll
    for (int j = 0; j < 8; j++){ int k = lane + j*32; c += h[k]*critic_W[k]; }
    #pragma unroll
    for (int s = 16; s > 0; s >>= 1) c += __shfl_xor_sync(0xffffffffu, c, s);
    #pragma unroll
    for (int j = 0; j < 8; j++){ int k = lane + j*32; o[2 + k] = h[k]; }
    float x0 = lg[lane], x1 = lg[lane + 32];
    float m = fmaxf(x0, x1);
    #pragma unroll
    for (int s = 16; s > 0; s >>= 1) m = fmaxf(m, __shfl_xor_sync(0xffffffffu, m, s));
    float e0 = expf(x0 - m), e1 = expf(x1 - m);
    float ssum = e0 + e1;
    #pragma unroll
    for (int s = 16; s > 0; s >>= 1) ssum += __shfl_xor_sync(0xffffffffu, ssum, s);
    float inv = 1.f / ssum;
    o[258 + lane] = e0 * inv;
    o[290 + lane] = e1 * inv;
    if (lane == 0){ o[0] = (float)actions[wid]; o[1] = c + critic_b[0]; }
}

extern "C" void kernel_launch(void* const* d_in, const int* in_sizes, int n_in,
                              void* d_out, int out_size)
{
    const float* values   = (const float*)d_in[0];
    const float* mdp      = (const float*)d_in[1];
    const int*   actions  = (const int*)  d_in[2];
    const int*   a0       = (const int*)  d_in[3];
    const float* h0       = (const float*)d_in[4];
    const float* emb_W    = (const float*)d_in[5];
    const float* emb_b    = (const float*)d_in[6];
    const float* gfw_Wih  = (const float*)d_in[7];
    const float* gfw_Whh  = (const float*)d_in[8];
    const float* gfw_bih  = (const float*)d_in[9];
    const float* gfw_bhh  = (const float*)d_in[10];
    const float* gbw_Wih  = (const float*)d_in[11];
    const float* gbw_Whh  = (const float*)d_in[12];
    const float* gbw_bih  = (const float*)d_in[13];
    const float* gbw_bhh  = (const float*)d_in[14];
    const float* f0_W     = (const float*)d_in[15];
    const float* f0_b     = (const float*)d_in[16];
    const float* f1_W     = (const float*)d_in[17];
    const float* f1_b     = (const float*)d_in[18];
    const float* cell_Wih = (const float*)d_in[19];
    const float* cell_Whh = (const float*)d_in[20];
    const float* cell_bih = (const float*)d_in[21];
    const float* cell_bhh = (const float*)d_in[22];
    const float* critic_W = (const float*)d_in[23];
    const float* critic_b = (const float*)d_in[24];
    const float* qg_W     = (const float*)d_in[25];
    const float* qg_b     = (const float*)d_in[26];
    float* out = (float*)d_out;

    float *pM, *pGIf, *pGIb, *pK, *pXin, *pX0, *pX1, *pGIc, *pH, *pKq;
    cudaGetSymbolAddress((void**)&pM,   d_M);
    cudaGetSymbolAddress((void**)&pGIf, d_GIf);
    cudaGetSymbolAddress((void**)&pGIb, d_GIb);
    cudaGetSymbolAddress((void**)&pK,   d_K);
    cudaGetSymbolAddress((void**)&pXin, d_Xin);
    cudaGetSymbolAddress((void**)&pX0,  d_X0);
    cudaGetSymbolAddress((void**)&pX1,  d_X1);
    cudaGetSymbolAddress((void**)&pGIc, d_GIc);
    cudaGetSymbolAddress((void**)&pH,   d_H);
    cudaGetSymbolAddress((void**)&pKq,  d_Kq);

    cudaFuncSetAttribute(enc_chain,  cudaFuncAttributeMaxDynamicSharedMemorySize, 163840);
    cudaFuncSetAttribute(cell_chain, cudaFuncAttributeMaxDynamicSharedMemorySize, 131072);

    zero_bars<<<1,1>>>();
    gemm_nn<false><<<dim3(4,128), 256>>>(mdp, 128, emb_W, 256, emb_b, pM, 256, 128);
    gemm_nn<false><<<dim3(12,128), 256>>>(pM, 256, gfw_Wih, 768, gfw_bih, pGIf, 768, 256);
    gemm_nn<false><<<dim3(12,128), 256>>>(pM, 256, gbw_Wih, 768, gbw_bih, pGIb, 768, 256);
    gather_xin<<<(T_*N_*80 + 255)/256, 256>>>(values, actions, a0);
    gemm_nn<true ><<<dim3(4,1024), 256>>>(pXin, 320, f0_W, 256, f0_b, pX0, 256, 320);
    gemm_nn<true ><<<dim3(4,1024), 256>>>(pX0, 256, f1_W, 256, f1_b, pX1, 256, 256);
    gemm_nn<false><<<dim3(12,1024), 256>>>(pX1, 256, cell_Wih, 768, cell_bih, pGIc, 768, 256);

    enc_chain<<<128, 256, 163840>>>(pGIf, pGIb, gfw_Whh, gbw_Whh, gfw_bhh, gbw_bhh, pK);
    cell_chain<<<128, 256, 131072>>>(pGIc, h0, cell_Whh, cell_bhh, pH);

    gemm_nn<false><<<dim3(8,1024), 256>>>(pH, 256, qg_W, 512, qg_b, pKq, 512, 256);
    logits_gemm<<<dim3(4,256), 256>>>();
    pack_out<<<T_*N_/8, 256>>>(actions, critic_W, critic_b, out);
}